// round 2
// baseline (speedup 1.0000x reference)
#include <cuda_runtime.h>
#include <cstdint>

// MaxUnpooling2D via gather:
//   B=16, H=W=128, C=64, UP=2 -> HO=WO=256.
//   mask[b,h,w,c] = ((2h+dh)*WO + (2w+dw))*C + c  (always inside its 2x2 window)
//   => out[b,ho,wo,c] = (mask[b,ho/2,wo/2,c] == (ho*WO+wo)*C + c) ? updates[b,ho/2,wo/2,c] : 0
//
// One thread per output float4 (C=64 -> 16 float4 per output pixel).
// Total output float4s: 16*256*256*16 = 16,777,216.

__global__ void __launch_bounds__(256, 8)
unpool_gather_kernel(const float4* __restrict__ upd,
                     const int4*  __restrict__ mask,
                     float4* __restrict__ out) {
    int g = blockIdx.x * blockDim.x + threadIdx.x;   // 0 .. 2^24-1

    // Decompose: g = (((b*256 + ho)*256 + wo)*16 + c4)
    int c4 = g & 15;          // which float4 within the 64 channels
    int wo = (g >> 4) & 255;
    int ho = (g >> 12) & 255;
    int b  = g >> 20;

    int h = ho >> 1;
    int w = wo >> 1;

    // input vec4 index: ((b*128 + h)*128 + w)*16 + c4
    int in_idx = ((((b << 7) + h) << 7) + w) * 16 + c4;

    int4   m = mask[in_idx];
    float4 u = upd[in_idx];

    // flat output element index of this thread's first channel:
    // (ho*256 + wo)*64 + c4*4
    int t = (((ho << 8) + wo) << 6) + (c4 << 2);

    float4 r;
    r.x = (m.x == t    ) ? u.x : 0.0f;
    r.y = (m.y == t + 1) ? u.y : 0.0f;
    r.z = (m.z == t + 2) ? u.z : 0.0f;
    r.w = (m.w == t + 3) ? u.w : 0.0f;

    out[g] = r;
}

extern "C" void kernel_launch(void* const* d_in, const int* in_sizes, int n_in,
                              void* d_out, int out_size) {
    const float4* upd  = (const float4*)d_in[0];   // updates: [16,128,128,64] f32
    const int4*   mask = (const int4*)  d_in[1];   // mask:    [16,128,128,64] i32
    float4*       out  = (float4*)d_out;           // out:     [16,256,256,64] f32

    // 16*256*256*64 / 4 = 16,777,216 float4s; 256 threads/block -> 65536 blocks
    const int total_vec4 = 16 * 256 * 256 * 16;
    const int threads = 256;
    const int blocks = total_vec4 / threads;       // 65536

    unpool_gather_kernel<<<blocks, threads>>>(upd, mask, out);
}

// round 3
// speedup vs baseline: 1.1241x; 1.1241x over previous
#include <cuda_runtime.h>
#include <cstdint>

// MaxUnpooling2D, gather formulation, one thread per 2x2 output window per c4:
//   B=16, H=W=128, C=64, UP=2 -> HO=WO=256.
//   mask[b,h,w,c] always lands inside its own 2x2 window, so for each of the
//   4 output positions: out = (mask == flat_idx(pos)) ? updates : 0.
//
// Thread (b,h,w,c4): 2 x LDG.128 (mask,upd), 4 x STG.128 (the 4 window slots).
// Total threads: 16*128*128*16 = 4,194,304.

__global__ void __launch_bounds__(256, 8)
unpool_window_kernel(const float4* __restrict__ upd,
                     const int4*  __restrict__ mask,
                     float4* __restrict__ out) {
    int g = blockIdx.x * blockDim.x + threadIdx.x;   // 0 .. 2^22-1

    int c4 = g & 15;            // float4 slot within the 64 channels
    int w  = (g >> 4) & 127;
    int h  = (g >> 11) & 127;
    int b  = g >> 18;

    // input vec4 index: ((b*128 + h)*128 + w)*16 + c4
    int in_idx = ((((b << 7) + h) << 7) + w) * 16 + c4;

    int4   m = mask[in_idx];
    float4 u = upd[in_idx];

    int ho = h << 1;            // top row of window
    int wo = w << 1;            // left col of window

    // flat output ELEMENT index of first channel at (ho, wo):
    int t00 = ((((ho << 8) + wo) << 6)) + (c4 << 2);
    int t01 = t00 + 64;         // (ho, wo+1): +C
    int t10 = t00 + (256 << 6); // (ho+1, wo): +WO*C = 16384
    int t11 = t10 + 64;

    // output VEC4 index of (b, ho, wo, c4):
    int o00 = ((((b << 8) + ho) << 8) + wo) * 16 + c4;
    int o01 = o00 + 16;         // wo+1: +C/4
    int o10 = o00 + 4096;       // ho+1: +WO*C/4
    int o11 = o10 + 16;

    float4 r;

    r.x = (m.x == t00    ) ? u.x : 0.0f;
    r.y = (m.y == t00 + 1) ? u.y : 0.0f;
    r.z = (m.z == t00 + 2) ? u.z : 0.0f;
    r.w = (m.w == t00 + 3) ? u.w : 0.0f;
    __stcs(&out[o00], r);

    r.x = (m.x == t01    ) ? u.x : 0.0f;
    r.y = (m.y == t01 + 1) ? u.y : 0.0f;
    r.z = (m.z == t01 + 2) ? u.z : 0.0f;
    r.w = (m.w == t01 + 3) ? u.w : 0.0f;
    __stcs(&out[o01], r);

    r.x = (m.x == t10    ) ? u.x : 0.0f;
    r.y = (m.y == t10 + 1) ? u.y : 0.0f;
    r.z = (m.z == t10 + 2) ? u.z : 0.0f;
    r.w = (m.w == t10 + 3) ? u.w : 0.0f;
    __stcs(&out[o10], r);

    r.x = (m.x == t11    ) ? u.x : 0.0f;
    r.y = (m.y == t11 + 1) ? u.y : 0.0f;
    r.z = (m.z == t11 + 2) ? u.z : 0.0f;
    r.w = (m.w == t11 + 3) ? u.w : 0.0f;
    __stcs(&out[o11], r);
}

extern "C" void kernel_launch(void* const* d_in, const int* in_sizes, int n_in,
                              void* d_out, int out_size) {
    const float4* upd  = (const float4*)d_in[0];   // updates: [16,128,128,64] f32
    const int4*   mask = (const int4*)  d_in[1];   // mask:    [16,128,128,64] i32
    float4*       out  = (float4*)d_out;           // out:     [16,256,256,64] f32

    const int total_threads = 16 * 128 * 128 * 16; // 4,194,304
    const int threads = 256;
    const int blocks = total_threads / threads;    // 16384

    unpool_window_kernel<<<blocks, threads>>>(upd, mask, out);
}